// round 6
// baseline (speedup 1.0000x reference)
#include <cuda_runtime.h>

#define B_      256
#define SEQ_    128
#define HID_    1024
#define NB_     256
#define NL_     3
#define G_      4              // k-values per CTA in pass 1
#define KG_     (NB_/G_)       // 64 k-groups
#define CHUNKS_ 8              // b-chunks (split softmax)
#define BPC_    (B_/CHUNKS_)   // 32 b per chunk

// Scratch (static device arrays only — no cudaMalloc allowed)
__device__ float g_part_u[NB_][CHUNKS_][HID_];   // 8 MB
__device__ float g_part_m[NB_][CHUNKS_];
__device__ float g_part_z[NB_][CHUNKS_];
__device__ float g_u[NB_][HID_];                 // 1 MB
__device__ float g_RH[NL_][HID_];                // R_w @ H_w  (3 x 1024)
__device__ float g_act[B_][HID_];                // slow-path activations
__device__ int   g_flag;                         // 1 iff alpha == 1 everywhere

// no-op spacer so ncu's fixed window (4th launch) lands on k1_partials
__global__ void k_noop() {}

// ---------------------------------------------------------------------------
// K1 (R1-proven structure): CTA = (4 k's, 32 b's). Thread t owns h4 = 4t.
// Per b: load x row + 4 S rows (1-deep prefetch), block-reduce 4 dots,
// online-softmax update of acc[4] (16 regs). 512 CTAs.
// ---------------------------------------------------------------------------
__global__ __launch_bounds__(256) void k1_partials(
    const float* __restrict__ ee, const float* __restrict__ S)
{
    const int kg = blockIdx.x;
    const int c  = blockIdx.y;
    const int t  = threadIdx.x;
    const int h4 = t * 4;
    const int b0 = c * BPC_;
    const int kbase = kg * G_;

    __shared__ float4 red[8];
    __shared__ float4 bcast;

    float4 acc[G_];
    float m[G_], z[G_];
#pragma unroll
    for (int g = 0; g < G_; g++) {
        acc[g] = make_float4(0.f, 0.f, 0.f, 0.f);
        m[g] = -3.0e38f;
        z[g] = 0.f;
    }

    // prime the pipeline
    float4 xv = *(const float4*)(ee + (size_t)b0 * SEQ_ * HID_ + h4);
    float4 sv[G_];
#pragma unroll
    for (int g = 0; g < G_; g++)
        sv[g] = *(const float4*)(S + ((size_t)b0 * NB_ + kbase + g) * HID_ + h4);

    for (int bi = 0; bi < BPC_; bi++) {
        // prefetch next b while we reduce the current one
        float4 xv_n = xv;
        float4 sv_n[G_];
#pragma unroll
        for (int g = 0; g < G_; g++) sv_n[g] = sv[g];
        if (bi + 1 < BPC_) {
            const int bn = b0 + bi + 1;
            xv_n = *(const float4*)(ee + (size_t)bn * SEQ_ * HID_ + h4);
#pragma unroll
            for (int g = 0; g < G_; g++)
                sv_n[g] = *(const float4*)(S + ((size_t)bn * NB_ + kbase + g) * HID_ + h4);
        }

        // 4 partial dots (one per k) packed in a float4
        float4 d;
        d.x = xv.x*sv[0].x + xv.y*sv[0].y + xv.z*sv[0].z + xv.w*sv[0].w;
        d.y = xv.x*sv[1].x + xv.y*sv[1].y + xv.z*sv[1].z + xv.w*sv[1].w;
        d.z = xv.x*sv[2].x + xv.y*sv[2].y + xv.z*sv[2].z + xv.w*sv[2].w;
        d.w = xv.x*sv[3].x + xv.y*sv[3].y + xv.z*sv[3].z + xv.w*sv[3].w;
#pragma unroll
        for (int off = 16; off > 0; off >>= 1) {
            d.x += __shfl_xor_sync(0xffffffffu, d.x, off);
            d.y += __shfl_xor_sync(0xffffffffu, d.y, off);
            d.z += __shfl_xor_sync(0xffffffffu, d.z, off);
            d.w += __shfl_xor_sync(0xffffffffu, d.w, off);
        }
        if ((t & 31) == 0) red[t >> 5] = d;
        __syncthreads();
        if (t == 0) {
            float4 s = red[0];
#pragma unroll
            for (int w2 = 1; w2 < 8; w2++) {
                float4 r = red[w2];
                s.x += r.x; s.y += r.y; s.z += r.z; s.w += r.w;
            }
            bcast = s;
        }
        __syncthreads();
        const float4 sc = bcast;
        const float scv[4] = { sc.x, sc.y, sc.z, sc.w };

#pragma unroll
        for (int g = 0; g < G_; g++) {
            const float s_ = scv[g];
            if (s_ > m[g]) {           // block-uniform branch
                const float cf = __expf(m[g] - s_);   // first iter: exp(-huge)=0
                z[g] = z[g] * cf + 1.f;
                acc[g].x = acc[g].x * cf + sv[g].x;
                acc[g].y = acc[g].y * cf + sv[g].y;
                acc[g].z = acc[g].z * cf + sv[g].z;
                acc[g].w = acc[g].w * cf + sv[g].w;
                m[g] = s_;
            } else {
                const float w = __expf(s_ - m[g]);
                z[g] += w;
                acc[g].x += w * sv[g].x;
                acc[g].y += w * sv[g].y;
                acc[g].z += w * sv[g].z;
                acc[g].w += w * sv[g].w;
            }
        }
        xv = xv_n;
#pragma unroll
        for (int g = 0; g < G_; g++) sv[g] = sv_n[g];
    }

#pragma unroll
    for (int g = 0; g < G_; g++) {
        const int k = kbase + g;
        *(float4*)&g_part_u[k][c][h4] = acc[g];
        if (t == 0) { g_part_m[k][c] = m[g]; g_part_z[k][c] = z[g]; }
    }
}

// ---------------------------------------------------------------------------
// KMIX: blocks 0..255 combine split-softmax partials into u[k][:]
//       (block 0 also computes the alpha==1 flag);
//       blocks 256..258 compute RH[l][:] = R_w[l] @ H_w.
// ---------------------------------------------------------------------------
__global__ __launch_bounds__(256) void kmix(
    const float* __restrict__ alpha, const float* __restrict__ Rw,
    const float* __restrict__ Hw)
{
    const int bid = blockIdx.x;
    const int t = threadIdx.x;

    if (bid < NB_) {
        const int k = bid;
        const int h4 = t * 4;

        if (k == 0) {
            int ok = 1;
#pragma unroll
            for (int r = 0; r < 4; r++) ok &= (alpha[h4 + r] == 1.0f);
            ok = __syncthreads_and(ok);
            if (t == 0) g_flag = ok;
        }

        float m = -3.0e38f;
#pragma unroll
        for (int c = 0; c < CHUNKS_; c++) m = fmaxf(m, g_part_m[k][c]);
        float Z = 0.f, w[CHUNKS_];
#pragma unroll
        for (int c = 0; c < CHUNKS_; c++) {
            w[c] = __expf(g_part_m[k][c] - m);
            Z += g_part_z[k][c] * w[c];
        }
        const float inv = 1.f / Z;
        float4 s = make_float4(0.f, 0.f, 0.f, 0.f);
#pragma unroll
        for (int c = 0; c < CHUNKS_; c++) {
            const float4 p = *(const float4*)&g_part_u[k][c][h4];
            const float ww = w[c] * inv;
            s.x += ww * p.x; s.y += ww * p.y; s.z += ww * p.z; s.w += ww * p.w;
        }
        *(float4*)&g_u[k][h4] = s;
    } else {
        const int l = bid - NB_;
        const int j4 = t * 4;
        float4 s = make_float4(0.f, 0.f, 0.f, 0.f);
#pragma unroll 8
        for (int h = 0; h < HID_; h++) {
            const float r = __ldg(Rw + l * HID_ + h);
            const float4 hv = *(const float4*)(Hw + (size_t)h * HID_ + j4);
            s.x += r * hv.x; s.y += r * hv.y; s.z += r * hv.z; s.w += r * hv.w;
        }
        *(float4*)&g_RH[l][j4] = s;
    }
}

// ---------------------------------------------------------------------------
// Fast path (alpha == 1): out[i][l] = x[i]·R_w[l] + u[i]·RH[l]
// ---------------------------------------------------------------------------
__global__ __launch_bounds__(256) void k_fast(
    const float* __restrict__ ee, const float* __restrict__ Rw,
    float* __restrict__ out)
{
    if (!g_flag) return;
    const int w = (blockIdx.x * 256 + threadIdx.x) >> 5;
    if (w >= B_ * NL_) return;
    const int i = w / NL_;
    const int l = w % NL_;
    const int lane = threadIdx.x & 31;
    const float* xr = ee + (size_t)i * SEQ_ * HID_;
    float s = 0.f;
#pragma unroll
    for (int j0 = 0; j0 < HID_; j0 += 128) {
        const int j = j0 + lane * 4;
        const float4 xv = *(const float4*)(xr + j);
        const float4 rv = *(const float4*)(Rw + l * HID_ + j);
        const float4 uv = *(const float4*)&g_u[i][j];
        const float4 gv = *(const float4*)&g_RH[l][j];
        s += xv.x * rv.x + xv.y * rv.y + xv.z * rv.z + xv.w * rv.w
           + uv.x * gv.x + uv.y * gv.y + uv.z * gv.z + uv.w * gv.w;
    }
#pragma unroll
    for (int off = 16; off > 0; off >>= 1)
        s += __shfl_xor_sync(0xffffffffu, s, off);
    if (lane == 0) out[i * NL_ + l] = s;
}

// ---------------------------------------------------------------------------
// Slow path (general alpha): v = x + u@H^T, act = PReLU(v) -> g_act.
// ---------------------------------------------------------------------------
__global__ __launch_bounds__(256) void k3_full(
    const float* __restrict__ ee, const float* __restrict__ Hw,
    const float* __restrict__ alpha)
{
    if (g_flag) return;
    __shared__ float Us[32][33];
    __shared__ float Hs[32][33];
    const int t  = threadIdx.x;
    const int tx = t & 15, ty = t >> 4;
    const int i0 = blockIdx.x * 32, h0 = blockIdx.y * 32;
    const int lr = t >> 3;
    const int lc = (t & 7) * 4;
    float acc00 = 0.f, acc01 = 0.f, acc10 = 0.f, acc11 = 0.f;

    for (int kk = 0; kk < HID_; kk += 32) {
        const float4 uu = *(const float4*)&g_u[i0 + lr][kk + lc];
        const float4 hh = *(const float4*)(Hw + (size_t)(h0 + lr) * HID_ + kk + lc);
        Us[lr][lc] = uu.x; Us[lr][lc+1] = uu.y; Us[lr][lc+2] = uu.z; Us[lr][lc+3] = uu.w;
        Hs[lr][lc] = hh.x; Hs[lr][lc+1] = hh.y; Hs[lr][lc+2] = hh.z; Hs[lr][lc+3] = hh.w;
        __syncthreads();
#pragma unroll
        for (int j = 0; j < 32; j++) {
            const float a0 = Us[ty*2][j],   a1 = Us[ty*2+1][j];
            const float b0 = Hs[tx*2][j],   b1 = Hs[tx*2+1][j];
            acc00 += a0*b0; acc01 += a0*b1; acc10 += a1*b0; acc11 += a1*b1;
        }
        __syncthreads();
    }
    const float accs[2][2] = { {acc00, acc01}, {acc10, acc11} };
#pragma unroll
    for (int ii = 0; ii < 2; ii++)
#pragma unroll
        for (int jj = 0; jj < 2; jj++) {
            const int i = i0 + ty*2 + ii;
            const int h = h0 + tx*2 + jj;
            const float v = accs[ii][jj] + ee[(size_t)i * SEQ_ * HID_ + h];
            g_act[i][h] = (v >= 0.f) ? v : alpha[h] * v;
        }
}

__global__ __launch_bounds__(256) void k4_full(
    const float* __restrict__ Rw, float* __restrict__ out)
{
    if (g_flag) return;
    const int w = (blockIdx.x * 256 + threadIdx.x) >> 5;
    if (w >= B_ * NL_) return;
    const int i = w / NL_;
    const int l = w % NL_;
    const int lane = threadIdx.x & 31;
    float s = 0.f;
#pragma unroll 8
    for (int j = lane; j < HID_; j += 32)
        s += g_act[i][j] * Rw[l * HID_ + j];
#pragma unroll
    for (int off = 16; off > 0; off >>= 1)
        s += __shfl_xor_sync(0xffffffffu, s, off);
    if (lane == 0) out[i * NL_ + l] = s;
}

// ---------------------------------------------------------------------------
extern "C" void kernel_launch(void* const* d_in, const int* in_sizes, int n_in,
                              void* d_out, int out_size)
{
    const float* ee = (const float*)d_in[0];   // (256,128,1024)
    const float* S  = (const float*)d_in[1];   // (256, 256*1024)
    const float* Hw = (const float*)d_in[2];   // (1024,1024)
    const float* Rw = (const float*)d_in[3];   // (3,1024)
    const float* al = (const float*)d_in[4];   // (1024,)
    float* out = (float*)d_out;                // (256,3)

    // 3 no-op spacers: ncu's fixed window profiles our 4th launch -> k1.
    k_noop<<<1, 32>>>();
    k_noop<<<1, 32>>>();
    k_noop<<<1, 32>>>();

    k1_partials<<<dim3(KG_, CHUNKS_), 256>>>(ee, S);
    kmix<<<NB_ + NL_, 256>>>(al, Rw, Hw);
    k3_full<<<dim3(B_ / 32, HID_ / 32), 256>>>(ee, Hw, al);
    k4_full<<<(B_ * NL_ * 32) / 256, 256>>>(Rw, out);
    k_fast<<<(B_ * NL_ * 32) / 256, 256>>>(ee, Rw, out);
}

// round 7
// speedup vs baseline: 2.8401x; 2.8401x over previous
#include <cuda_runtime.h>

#define B_      256
#define SEQ_    128
#define HID_    1024
#define NB_     256
#define NL_     3
#define G_      4              // k-values per CTA in pass 1
#define KG_     (NB_/G_)       // 64 k-groups
#define CHUNKS_ 16             // b-chunks (split softmax)
#define BPC_    (B_/CHUNKS_)   // 16 b per chunk
#define RHS_    32             // h-splits for R@H partial kernel

// Scratch (static device arrays only — no cudaMalloc allowed)
__device__ float g_part_u[NB_][CHUNKS_][HID_];   // 16 MB
__device__ float g_part_m[NB_][CHUNKS_];
__device__ float g_part_z[NB_][CHUNKS_];
__device__ float g_u[NB_][HID_];                 // 1 MB
__device__ float g_RHp[RHS_][NL_][HID_];         // partials of R_w @ H_w
__device__ float g_RH[NL_][HID_];                // R_w @ H_w  (3 x 1024)
__device__ float g_act[B_][HID_];                // slow-path activations
__device__ int   g_flag;                         // 1 iff alpha == 1 everywhere

// no-op spacer so ncu's fixed window (4th launch) lands on k1_partials
__global__ void k_noop() {}

// ---------------------------------------------------------------------------
// K1: CTA = (4 k's, 16 b's), 1024 CTAs. Thread t owns h4 = 4t.
// Per b: load x row + 4 S rows (1-deep prefetch), ONE __syncthreads per b
// (double-buffered warp-partials; every thread sums the 8 partials itself),
// online-softmax update of acc[4].
// ---------------------------------------------------------------------------
__global__ __launch_bounds__(256) void k1_partials(
    const float* __restrict__ ee, const float* __restrict__ S)
{
    const int kg = blockIdx.x;
    const int c  = blockIdx.y;
    const int t  = threadIdx.x;
    const int h4 = t * 4;
    const int b0 = c * BPC_;
    const int kbase = kg * G_;

    __shared__ float4 red[2][8];   // double-buffered warp partials

    float4 acc[G_];
    float m[G_], z[G_];
#pragma unroll
    for (int g = 0; g < G_; g++) {
        acc[g] = make_float4(0.f, 0.f, 0.f, 0.f);
        m[g] = -3.0e38f;
        z[g] = 0.f;
    }

    // prime the pipeline
    float4 xv = *(const float4*)(ee + (size_t)b0 * SEQ_ * HID_ + h4);
    float4 sv[G_];
#pragma unroll
    for (int g = 0; g < G_; g++)
        sv[g] = *(const float4*)(S + ((size_t)b0 * NB_ + kbase + g) * HID_ + h4);

    for (int bi = 0; bi < BPC_; bi++) {
        // prefetch next b while we reduce the current one
        float4 xv_n = xv;
        float4 sv_n[G_];
#pragma unroll
        for (int g = 0; g < G_; g++) sv_n[g] = sv[g];
        if (bi + 1 < BPC_) {
            const int bn = b0 + bi + 1;
            xv_n = *(const float4*)(ee + (size_t)bn * SEQ_ * HID_ + h4);
#pragma unroll
            for (int g = 0; g < G_; g++)
                sv_n[g] = *(const float4*)(S + ((size_t)bn * NB_ + kbase + g) * HID_ + h4);
        }

        // 4 partial dots (one per k) packed in a float4
        float4 d;
        d.x = xv.x*sv[0].x + xv.y*sv[0].y + xv.z*sv[0].z + xv.w*sv[0].w;
        d.y = xv.x*sv[1].x + xv.y*sv[1].y + xv.z*sv[1].z + xv.w*sv[1].w;
        d.z = xv.x*sv[2].x + xv.y*sv[2].y + xv.z*sv[2].z + xv.w*sv[2].w;
        d.w = xv.x*sv[3].x + xv.y*sv[3].y + xv.z*sv[3].z + xv.w*sv[3].w;
#pragma unroll
        for (int off = 16; off > 0; off >>= 1) {
            d.x += __shfl_xor_sync(0xffffffffu, d.x, off);
            d.y += __shfl_xor_sync(0xffffffffu, d.y, off);
            d.z += __shfl_xor_sync(0xffffffffu, d.z, off);
            d.w += __shfl_xor_sync(0xffffffffu, d.w, off);
        }
        if ((t & 31) == 0) red[bi & 1][t >> 5] = d;
        __syncthreads();   // red[bi&1] published; red[1-(bi&1)] free for next iter

        float4 sc = red[bi & 1][0];
#pragma unroll
        for (int w2 = 1; w2 < 8; w2++) {
            const float4 r = red[bi & 1][w2];
            sc.x += r.x; sc.y += r.y; sc.z += r.z; sc.w += r.w;
        }
        const float scv[4] = { sc.x, sc.y, sc.z, sc.w };

#pragma unroll
        for (int g = 0; g < G_; g++) {
            const float s_ = scv[g];
            if (s_ > m[g]) {           // block-uniform branch
                const float cf = __expf(m[g] - s_);   // first iter: exp(-huge)=0
                z[g] = z[g] * cf + 1.f;
                acc[g].x = acc[g].x * cf + sv[g].x;
                acc[g].y = acc[g].y * cf + sv[g].y;
                acc[g].z = acc[g].z * cf + sv[g].z;
                acc[g].w = acc[g].w * cf + sv[g].w;
                m[g] = s_;
            } else {
                const float w = __expf(s_ - m[g]);
                z[g] += w;
                acc[g].x += w * sv[g].x;
                acc[g].y += w * sv[g].y;
                acc[g].z += w * sv[g].z;
                acc[g].w += w * sv[g].w;
            }
        }
        xv = xv_n;
#pragma unroll
        for (int g = 0; g < G_; g++) sv[g] = sv_n[g];
    }

#pragma unroll
    for (int g = 0; g < G_; g++) {
        const int k = kbase + g;
        *(float4*)&g_part_u[k][c][h4] = acc[g];
        if (t == 0) { g_part_m[k][c] = m[g]; g_part_z[k][c] = z[g]; }
    }
}

// ---------------------------------------------------------------------------
// K2: combine split-softmax partials per k into u[k][:].
// Block 0 also computes the alpha==1 flag.
// ---------------------------------------------------------------------------
__global__ __launch_bounds__(256) void k2_combine(const float* __restrict__ alpha)
{
    const int k = blockIdx.x;
    const int t = threadIdx.x;
    const int h4 = t * 4;

    if (k == 0) {
        int ok = 1;
#pragma unroll
        for (int r = 0; r < 4; r++) ok &= (alpha[h4 + r] == 1.0f);
        ok = __syncthreads_and(ok);
        if (t == 0) g_flag = ok;
    }

    float m = -3.0e38f;
#pragma unroll
    for (int c = 0; c < CHUNKS_; c++) m = fmaxf(m, g_part_m[k][c]);
    float Z = 0.f, w[CHUNKS_];
#pragma unroll
    for (int c = 0; c < CHUNKS_; c++) {
        w[c] = __expf(g_part_m[k][c] - m);
        Z += g_part_z[k][c] * w[c];
    }
    const float inv = 1.f / Z;
    float4 s = make_float4(0.f, 0.f, 0.f, 0.f);
#pragma unroll
    for (int c = 0; c < CHUNKS_; c++) {
        const float4 p = *(const float4*)&g_part_u[k][c][h4];
        const float ww = w[c] * inv;
        s.x += ww * p.x; s.y += ww * p.y; s.z += ww * p.z; s.w += ww * p.w;
    }
    *(float4*)&g_u[k][h4] = s;
}

// ---------------------------------------------------------------------------
// R@H stage 1 (proven): RHp[hs][l][j] = sum over 32 h of R[l,h]*H[h,j].
// 32 blocks -> per-warp loop is only 32 iterations (latency amortized).
// ---------------------------------------------------------------------------
__global__ __launch_bounds__(256) void k_rh1(
    const float* __restrict__ Rw, const float* __restrict__ Hw)
{
    const int hs = blockIdx.x;
    const int j4 = threadIdx.x * 4;
    float4 a0 = make_float4(0,0,0,0), a1 = a0, a2 = a0;
    const int hstep = HID_ / RHS_;   // 32
#pragma unroll 4
    for (int hh = 0; hh < hstep; hh++) {
        const int h = hs * hstep + hh;
        const float4 hv = *(const float4*)(Hw + (size_t)h * HID_ + j4);
        const float r0 = Rw[0 * HID_ + h];
        const float r1 = Rw[1 * HID_ + h];
        const float r2 = Rw[2 * HID_ + h];
        a0.x += r0*hv.x; a0.y += r0*hv.y; a0.z += r0*hv.z; a0.w += r0*hv.w;
        a1.x += r1*hv.x; a1.y += r1*hv.y; a1.z += r1*hv.z; a1.w += r1*hv.w;
        a2.x += r2*hv.x; a2.y += r2*hv.y; a2.z += r2*hv.z; a2.w += r2*hv.w;
    }
    *(float4*)&g_RHp[hs][0][j4] = a0;
    *(float4*)&g_RHp[hs][1][j4] = a1;
    *(float4*)&g_RHp[hs][2][j4] = a2;
}

// R@H stage 2: reduce the RHS_ partials. 3072 outputs.
__global__ __launch_bounds__(256) void k_rh2()
{
    const int idx = blockIdx.x * 256 + threadIdx.x;   // 0..3071
    const int l = idx >> 10;
    const int j = idx & 1023;
    float s = 0.f;
#pragma unroll
    for (int hs = 0; hs < RHS_; hs++) s += g_RHp[hs][l][j];
    g_RH[l][j] = s;
}

// ---------------------------------------------------------------------------
// Fast path (alpha == 1): out[i][l] = x[i]·R_w[l] + u[i]·RH[l]
// ---------------------------------------------------------------------------
__global__ __launch_bounds__(256) void k_fast(
    const float* __restrict__ ee, const float* __restrict__ Rw,
    float* __restrict__ out)
{
    if (!g_flag) return;
    const int w = (blockIdx.x * 256 + threadIdx.x) >> 5;
    if (w >= B_ * NL_) return;
    const int i = w / NL_;
    const int l = w % NL_;
    const int lane = threadIdx.x & 31;
    const float* xr = ee + (size_t)i * SEQ_ * HID_;
    float s = 0.f;
#pragma unroll
    for (int j0 = 0; j0 < HID_; j0 += 128) {
        const int j = j0 + lane * 4;
        const float4 xv = *(const float4*)(xr + j);
        const float4 rv = *(const float4*)(Rw + l * HID_ + j);
        const float4 uv = *(const float4*)&g_u[i][j];
        const float4 gv = *(const float4*)&g_RH[l][j];
        s += xv.x * rv.x + xv.y * rv.y + xv.z * rv.z + xv.w * rv.w
           + uv.x * gv.x + uv.y * gv.y + uv.z * gv.z + uv.w * gv.w;
    }
#pragma unroll
    for (int off = 16; off > 0; off >>= 1)
        s += __shfl_xor_sync(0xffffffffu, s, off);
    if (lane == 0) out[i * NL_ + l] = s;
}

// ---------------------------------------------------------------------------
// Slow path (general alpha): v = x + u@H^T, act = PReLU(v) -> g_act.
// ---------------------------------------------------------------------------
__global__ __launch_bounds__(256) void k3_full(
    const float* __restrict__ ee, const float* __restrict__ Hw,
    const float* __restrict__ alpha)
{
    if (g_flag) return;
    __shared__ float Us[32][33];
    __shared__ float Hs[32][33];
    const int t  = threadIdx.x;
    const int tx = t & 15, ty = t >> 4;
    const int i0 = blockIdx.x * 32, h0 = blockIdx.y * 32;
    const int lr = t >> 3;
    const int lc = (t & 7) * 4;
    float acc00 = 0.f, acc01 = 0.f, acc10 = 0.f, acc11 = 0.f;

    for (int kk = 0; kk < HID_; kk += 32) {
        const float4 uu = *(const float4*)&g_u[i0 + lr][kk + lc];
        const float4 hh = *(const float4*)(Hw + (size_t)(h0 + lr) * HID_ + kk + lc);
        Us[lr][lc] = uu.x; Us[lr][lc+1] = uu.y; Us[lr][lc+2] = uu.z; Us[lr][lc+3] = uu.w;
        Hs[lr][lc] = hh.x; Hs[lr][lc+1] = hh.y; Hs[lr][lc+2] = hh.z; Hs[lr][lc+3] = hh.w;
        __syncthreads();
#pragma unroll
        for (int j = 0; j < 32; j++) {
            const float a0 = Us[ty*2][j],   a1 = Us[ty*2+1][j];
            const float b0 = Hs[tx*2][j],   b1 = Hs[tx*2+1][j];
            acc00 += a0*b0; acc01 += a0*b1; acc10 += a1*b0; acc11 += a1*b1;
        }
        __syncthreads();
    }
    const float accs[2][2] = { {acc00, acc01}, {acc10, acc11} };
#pragma unroll
    for (int ii = 0; ii < 2; ii++)
#pragma unroll
        for (int jj = 0; jj < 2; jj++) {
            const int i = i0 + ty*2 + ii;
            const int h = h0 + tx*2 + jj;
            const float v = accs[ii][jj] + ee[(size_t)i * SEQ_ * HID_ + h];
            g_act[i][h] = (v >= 0.f) ? v : alpha[h] * v;
        }
}

__global__ __launch_bounds__(256) void k4_full(
    const float* __restrict__ Rw, float* __restrict__ out)
{
    if (g_flag) return;
    const int w = (blockIdx.x * 256 + threadIdx.x) >> 5;
    if (w >= B_ * NL_) return;
    const int i = w / NL_;
    const int l = w % NL_;
    const int lane = threadIdx.x & 31;
    float s = 0.f;
#pragma unroll 8
    for (int j = lane; j < HID_; j += 32)
        s += g_act[i][j] * Rw[l * HID_ + j];
#pragma unroll
    for (int off = 16; off > 0; off >>= 1)
        s += __shfl_xor_sync(0xffffffffu, s, off);
    if (lane == 0) out[i * NL_ + l] = s;
}

// ---------------------------------------------------------------------------
extern "C" void kernel_launch(void* const* d_in, const int* in_sizes, int n_in,
                              void* d_out, int out_size)
{
    const float* ee = (const float*)d_in[0];   // (256,128,1024)
    const float* S  = (const float*)d_in[1];   // (256, 256*1024)
    const float* Hw = (const float*)d_in[2];   // (1024,1024)
    const float* Rw = (const float*)d_in[3];   // (3,1024)
    const float* al = (const float*)d_in[4];   // (1024,)
    float* out = (float*)d_out;                // (256,3)

    // 3 no-op spacers: ncu's fixed window profiles our 4th launch -> k1.
    k_noop<<<1, 32>>>();
    k_noop<<<1, 32>>>();
    k_noop<<<1, 32>>>();

    k1_partials<<<dim3(KG_, CHUNKS_), 256>>>(ee, S);
    k2_combine<<<NB_, 256>>>(al);
    k_rh1<<<RHS_, 256>>>(Rw, Hw);
    k_rh2<<<(NL_ * HID_) / 256, 256>>>();
    k3_full<<<dim3(B_ / 32, HID_ / 32), 256>>>(ee, Hw, al);
    k4_full<<<(B_ * NL_ * 32) / 256, 256>>>(Rw, out);
    k_fast<<<(B_ * NL_ * 32) / 256, 256>>>(ee, Rw, out);
}

// round 8
// speedup vs baseline: 3.5804x; 1.2607x over previous
#include <cuda_runtime.h>
#include <cstdint>

#define B_      256
#define SEQ_    128
#define HID_    1024
#define NB_     256
#define NL_     3
#define G_      2              // k-values per CTA in pass 1
#define KG_     (NB_/G_)       // 128 k-groups
#define CHUNKS_ 8              // b-chunks (split softmax)
#define BPC_    (B_/CHUNKS_)   // 32 b per chunk
#define DEPTH_  4              // cp.async pipeline depth
#define RHS_    32             // h-splits for R@H partial work

// Scratch (static device arrays only — no cudaMalloc allowed)
__device__ float g_part_u[NB_][CHUNKS_][HID_];   // 8 MB
__device__ float g_part_m[NB_][CHUNKS_];
__device__ float g_part_z[NB_][CHUNKS_];
__device__ float g_u[NB_][HID_];                 // 1 MB
__device__ float g_RHp[RHS_][NL_][HID_];         // partials of R_w @ H_w
__device__ float g_RH[NL_][HID_];                // R_w @ H_w  (3 x 1024)
__device__ float g_act[B_][HID_];                // slow-path activations
__device__ int   g_flag;                         // 1 iff alpha == 1 everywhere

// no-op spacer so ncu's fixed window (4th launch) lands on k1_partials
__global__ void k_noop() {}

// ---- cp.async helpers -------------------------------------------------------
__device__ __forceinline__ uint32_t smem_u32(const void* p) {
    return (uint32_t)__cvta_generic_to_shared(p);
}
__device__ __forceinline__ void cp_async16(uint32_t dst, const void* src) {
    asm volatile("cp.async.cg.shared.global [%0], [%1], 16;\n" :: "r"(dst), "l"(src));
}
__device__ __forceinline__ void cp_commit() {
    asm volatile("cp.async.commit_group;\n" ::: "memory");
}
template <int N>
__device__ __forceinline__ void cp_wait() {
    asm volatile("cp.async.wait_group %0;\n" :: "n"(N) : "memory");
}

// ---------------------------------------------------------------------------
// K1: cp.async-pipelined online softmax. CTA = (2 k's, 32 b's), 1024 CTAs.
// Stage (12 KB) = x row + 2 S rows; DEPTH_=4 stages (48 KB) -> 4 CTA/SM.
// Each thread copies ONLY the bytes it reads (its h4 slice), so cp.async
// completion needs no barrier; the single barrier per b is the score reduce.
// In-flight bytes/SM ~ 144 KB -> DRAM-bound.
// ---------------------------------------------------------------------------
__global__ __launch_bounds__(256) void k1_partials(
    const float* __restrict__ ee, const float* __restrict__ S)
{
    extern __shared__ float sm[];         // [DEPTH_][3][HID_]
    __shared__ float2 red[2][8];          // double-buffered warp partials

    const int t     = threadIdx.x;
    const int w     = t >> 5;
    const int lane  = t & 31;
    const int kg    = blockIdx.x;
    const int c     = blockIdx.y;
    const int b0    = c * BPC_;
    const int kbase = kg * G_;
    const int h4    = t * 4;

    // issue one stage (x + 2 S rows, this thread's slice only)
    auto issue = [&](int stage, int b) {
        float* dst = sm + stage * 3 * HID_;
        cp_async16(smem_u32(dst + h4),
                   ee + (size_t)b * SEQ_ * HID_ + h4);
        cp_async16(smem_u32(dst + HID_ + h4),
                   S + ((size_t)b * NB_ + kbase) * HID_ + h4);
        cp_async16(smem_u32(dst + 2 * HID_ + h4),
                   S + ((size_t)b * NB_ + kbase + 1) * HID_ + h4);
    };

#pragma unroll
    for (int d = 0; d < DEPTH_; d++) { issue(d, b0 + d); cp_commit(); }

    float4 acc0 = make_float4(0.f, 0.f, 0.f, 0.f);
    float4 acc1 = make_float4(0.f, 0.f, 0.f, 0.f);
    float m0 = -3.0e38f, m1 = -3.0e38f, z0 = 0.f, z1 = 0.f;

    for (int bi = 0; bi < BPC_; bi++) {
        cp_wait<DEPTH_ - 1>();            // stage for bi complete (per-thread)

        float* st = sm + (bi & (DEPTH_ - 1)) * 3 * HID_;
        const float4 xv = *(const float4*)(st + h4);
        const float4 s0 = *(const float4*)(st + HID_ + h4);
        const float4 s1 = *(const float4*)(st + 2 * HID_ + h4);

        // refill this stage immediately (values already in regs; thread-own slots)
        const int bn = bi + DEPTH_;
        if (bn < BPC_) issue(bi & (DEPTH_ - 1), b0 + bn);
        cp_commit();                      // commit even when empty: keeps group count uniform

        // two partial dots
        float dx = xv.x*s0.x + xv.y*s0.y + xv.z*s0.z + xv.w*s0.w;
        float dy = xv.x*s1.x + xv.y*s1.y + xv.z*s1.z + xv.w*s1.w;
#pragma unroll
        for (int off = 16; off > 0; off >>= 1) {
            dx += __shfl_xor_sync(0xffffffffu, dx, off);
            dy += __shfl_xor_sync(0xffffffffu, dy, off);
        }
        if (lane == 0) red[bi & 1][w] = make_float2(dx, dy);
        __syncthreads();
        float sc0 = 0.f, sc1 = 0.f;
#pragma unroll
        for (int w2 = 0; w2 < 8; w2++) {
            const float2 r = red[bi & 1][w2];
            sc0 += r.x; sc1 += r.y;
        }

        // online softmax updates (block-uniform branches)
        if (sc0 > m0) {
            const float cf = __expf(m0 - sc0);
            z0 = z0 * cf + 1.f;
            acc0.x = acc0.x * cf + s0.x; acc0.y = acc0.y * cf + s0.y;
            acc0.z = acc0.z * cf + s0.z; acc0.w = acc0.w * cf + s0.w;
            m0 = sc0;
        } else {
            const float wg = __expf(sc0 - m0);
            z0 += wg;
            acc0.x += wg * s0.x; acc0.y += wg * s0.y;
            acc0.z += wg * s0.z; acc0.w += wg * s0.w;
        }
        if (sc1 > m1) {
            const float cf = __expf(m1 - sc1);
            z1 = z1 * cf + 1.f;
            acc1.x = acc1.x * cf + s1.x; acc1.y = acc1.y * cf + s1.y;
            acc1.z = acc1.z * cf + s1.z; acc1.w = acc1.w * cf + s1.w;
            m1 = sc1;
        } else {
            const float wg = __expf(sc1 - m1);
            z1 += wg;
            acc1.x += wg * s1.x; acc1.y += wg * s1.y;
            acc1.z += wg * s1.z; acc1.w += wg * s1.w;
        }
    }

    *(float4*)&g_part_u[kbase + 0][c][h4] = acc0;
    *(float4*)&g_part_u[kbase + 1][c][h4] = acc1;
    if (t == 0) {
        g_part_m[kbase + 0][c] = m0; g_part_z[kbase + 0][c] = z0;
        g_part_m[kbase + 1][c] = m1; g_part_z[kbase + 1][c] = z1;
    }
}

// ---------------------------------------------------------------------------
// K2: blocks 0..255 combine split-softmax partials into u[k][:]
//     (block 0 also computes the alpha==1 flag);
//     blocks 256..287 do the R@H stage-1 partials (32-row h-splits).
// ---------------------------------------------------------------------------
__global__ __launch_bounds__(256) void k2_combine(
    const float* __restrict__ alpha, const float* __restrict__ Rw,
    const float* __restrict__ Hw)
{
    const int bid = blockIdx.x;
    const int t = threadIdx.x;

    if (bid < NB_) {
        const int k = bid;
        const int h4 = t * 4;

        if (k == 0) {
            int ok = 1;
#pragma unroll
            for (int r = 0; r < 4; r++) ok &= (alpha[h4 + r] == 1.0f);
            ok = __syncthreads_and(ok);
            if (t == 0) g_flag = ok;
        }

        float m = -3.0e38f;
#pragma unroll
        for (int c = 0; c < CHUNKS_; c++) m = fmaxf(m, g_part_m[k][c]);
        float Z = 0.f, w[CHUNKS_];
#pragma unroll
        for (int c = 0; c < CHUNKS_; c++) {
            w[c] = __expf(g_part_m[k][c] - m);
            Z += g_part_z[k][c] * w[c];
        }
        const float inv = 1.f / Z;
        float4 s = make_float4(0.f, 0.f, 0.f, 0.f);
#pragma unroll
        for (int c = 0; c < CHUNKS_; c++) {
            const float4 p = *(const float4*)&g_part_u[k][c][h4];
            const float ww = w[c] * inv;
            s.x += ww * p.x; s.y += ww * p.y; s.z += ww * p.z; s.w += ww * p.w;
        }
        *(float4*)&g_u[k][h4] = s;
    } else {
        // R@H stage 1: hs = bid-256, 32 h-rows
        const int hs = bid - NB_;
        const int j4 = t * 4;
        float4 a0 = make_float4(0,0,0,0), a1 = a0, a2 = a0;
        const int hstep = HID_ / RHS_;   // 32
#pragma unroll 4
        for (int hh = 0; hh < hstep; hh++) {
            const int h = hs * hstep + hh;
            const float4 hv = *(const float4*)(Hw + (size_t)h * HID_ + j4);
            const float r0 = Rw[0 * HID_ + h];
            const float r1 = Rw[1 * HID_ + h];
            const float r2 = Rw[2 * HID_ + h];
            a0.x += r0*hv.x; a0.y += r0*hv.y; a0.z += r0*hv.z; a0.w += r0*hv.w;
            a1.x += r1*hv.x; a1.y += r1*hv.y; a1.z += r1*hv.z; a1.w += r1*hv.w;
            a2.x += r2*hv.x; a2.y += r2*hv.y; a2.z += r2*hv.z; a2.w += r2*hv.w;
        }
        *(float4*)&g_RHp[hs][0][j4] = a0;
        *(float4*)&g_RHp[hs][1][j4] = a1;
        *(float4*)&g_RHp[hs][2][j4] = a2;
    }
}

// R@H stage 2: reduce the RHS_ partials. 3072 outputs.
__global__ __launch_bounds__(256) void k_rh2()
{
    const int idx = blockIdx.x * 256 + threadIdx.x;   // 0..3071
    const int l = idx >> 10;
    const int j = idx & 1023;
    float s = 0.f;
#pragma unroll
    for (int hs = 0; hs < RHS_; hs++) s += g_RHp[hs][l][j];
    g_RH[l][j] = s;
}

// ---------------------------------------------------------------------------
// Slow path (general alpha): v = x + u@H^T, act = PReLU(v) -> g_act.
// Early-exits when flag==1.
// ---------------------------------------------------------------------------
__global__ __launch_bounds__(256) void k3_full(
    const float* __restrict__ ee, const float* __restrict__ Hw,
    const float* __restrict__ alpha)
{
    if (g_flag) return;
    __shared__ float Us[32][33];
    __shared__ float Hs[32][33];
    const int t  = threadIdx.x;
    const int tx = t & 15, ty = t >> 4;
    const int i0 = blockIdx.x * 32, h0 = blockIdx.y * 32;
    const int lr = t >> 3;
    const int lc = (t & 7) * 4;
    float acc00 = 0.f, acc01 = 0.f, acc10 = 0.f, acc11 = 0.f;

    for (int kk = 0; kk < HID_; kk += 32) {
        const float4 uu = *(const float4*)&g_u[i0 + lr][kk + lc];
        const float4 hh = *(const float4*)(Hw + (size_t)(h0 + lr) * HID_ + kk + lc);
        Us[lr][lc] = uu.x; Us[lr][lc+1] = uu.y; Us[lr][lc+2] = uu.z; Us[lr][lc+3] = uu.w;
        Hs[lr][lc] = hh.x; Hs[lr][lc+1] = hh.y; Hs[lr][lc+2] = hh.z; Hs[lr][lc+3] = hh.w;
        __syncthreads();
#pragma unroll
        for (int j = 0; j < 32; j++) {
            const float a0 = Us[ty*2][j],   a1 = Us[ty*2+1][j];
            const float b0 = Hs[tx*2][j],   b1 = Hs[tx*2+1][j];
            acc00 += a0*b0; acc01 += a0*b1; acc10 += a1*b0; acc11 += a1*b1;
        }
        __syncthreads();
    }
    const float accs[2][2] = { {acc00, acc01}, {acc10, acc11} };
#pragma unroll
    for (int ii = 0; ii < 2; ii++)
#pragma unroll
        for (int jj = 0; jj < 2; jj++) {
            const int i = i0 + ty*2 + ii;
            const int h = h0 + tx*2 + jj;
            const float v = accs[ii][jj] + ee[(size_t)i * SEQ_ * HID_ + h];
            g_act[i][h] = (v >= 0.f) ? v : alpha[h] * v;
        }
}

// ---------------------------------------------------------------------------
// K_OUT (merged fast/slow final): one warp per output (i,l).
//  flag==1: out = x[i]·R_w[l] + u[i]·RH[l]
//  flag==0: out = act[i]·R_w[l]
// ---------------------------------------------------------------------------
__global__ __launch_bounds__(256) void k_out(
    const float* __restrict__ ee, const float* __restrict__ Rw,
    float* __restrict__ out)
{
    const int w = (blockIdx.x * 256 + threadIdx.x) >> 5;
    if (w >= B_ * NL_) return;
    const int i = w / NL_;
    const int l = w % NL_;
    const int lane = threadIdx.x & 31;
    float s = 0.f;

    if (g_flag) {
        const float* xr = ee + (size_t)i * SEQ_ * HID_;
#pragma unroll
        for (int j0 = 0; j0 < HID_; j0 += 128) {
            const int j = j0 + lane * 4;
            const float4 xv = *(const float4*)(xr + j);
            const float4 rv = *(const float4*)(Rw + l * HID_ + j);
            const float4 uv = *(const float4*)&g_u[i][j];
            const float4 gv = *(const float4*)&g_RH[l][j];
            s += xv.x * rv.x + xv.y * rv.y + xv.z * rv.z + xv.w * rv.w
               + uv.x * gv.x + uv.y * gv.y + uv.z * gv.z + uv.w * gv.w;
        }
    } else {
#pragma unroll
        for (int j0 = 0; j0 < HID_; j0 += 128) {
            const int j = j0 + lane * 4;
            const float4 av = *(const float4*)&g_act[i][j];
            const float4 rv = *(const float4*)(Rw + l * HID_ + j);
            s += av.x * rv.x + av.y * rv.y + av.z * rv.z + av.w * rv.w;
        }
    }
#pragma unroll
    for (int off = 16; off > 0; off >>= 1)
        s += __shfl_xor_sync(0xffffffffu, s, off);
    if (lane == 0) out[i * NL_ + l] = s;
}

// ---------------------------------------------------------------------------
extern "C" void kernel_launch(void* const* d_in, const int* in_sizes, int n_in,
                              void* d_out, int out_size)
{
    const float* ee = (const float*)d_in[0];   // (256,128,1024)
    const float* S  = (const float*)d_in[1];   // (256, 256*1024)
    const float* Hw = (const float*)d_in[2];   // (1024,1024)
    const float* Rw = (const float*)d_in[3];   // (3,1024)
    const float* al = (const float*)d_in[4];   // (1024,)
    float* out = (float*)d_out;                // (256,3)

    const int smem_bytes = DEPTH_ * 3 * HID_ * sizeof(float);   // 48 KB
    cudaFuncSetAttribute(k1_partials,
                         cudaFuncAttributeMaxDynamicSharedMemorySize, smem_bytes);

    // 3 no-op spacers: ncu's fixed window profiles our 4th launch -> k1.
    k_noop<<<1, 32>>>();
    k_noop<<<1, 32>>>();
    k_noop<<<1, 32>>>();

    k1_partials<<<dim3(KG_, CHUNKS_), 256, smem_bytes>>>(ee, S);
    k2_combine<<<NB_ + RHS_, 256>>>(al, Rw, Hw);
    k_rh2<<<(NL_ * HID_) / 256, 256>>>();
    k3_full<<<dim3(B_ / 32, HID_ / 32), 256>>>(ee, Hw, al);
    k_out<<<(B_ * NL_ * 32) / 256, 256>>>(ee, Rw, out);
}